// round 16
// baseline (speedup 1.0000x reference)
#include <cuda_runtime.h>
#include <cuda_bf16.h>
#include <cstdint>

#define Bn 32
#define Tn 128
#define Kn 256
#define Hn 512
#define Vn 10000
#define BT (Bn*Tn)
#define G4n (4*Hn)
#define TWOK (2*Kn)
#define NVT 157              // ceil(Vn/64)

#define HALF_LOG_2PI 0.918938533204672741780329736406f

typedef unsigned long long ull;

// ---------------- static scratch ----------------
__device__ __align__(16) __nv_bfloat16 g_zb[BT*Kn];      // 2 MB
__device__ __align__(16) __nv_bfloat16 g_ZZb[BT*TWOK];   // 4 MB [z | z^2]
__device__ __align__(16) __nv_bfloat16 g_hb[BT*Hn];      // 4 MB
__device__ __align__(16) __nv_bfloat16 g_W2b[Vn*TWOK];   // 10 MB
__device__ __align__(16) __nv_bfloat16 g_wpb[Vn*Hn];     // 10 MB
__device__ __align__(16) __nv_bfloat16 g_wgb[Vn*Kn];     // 5 MB
__device__ __align__(16) __nv_bfloat16 g_wihb[G4n*Kn];   // 1 MB
__device__ __align__(16) float g_xproj[BT*G4n];          // 32 MB, layout [(js*128+t)*32+b][16r]
__device__ float g_cst[Vn];
__device__ float g_qzlp[BT];
__device__ float g_sumz2[BT];
__device__ float g_tgt[BT];
__device__ float g_part[3*NVT*BT];
__device__ float g_contrib[BT];
__device__ __align__(16) float g_hbuf[2][Hn*Bn];         // TRANSPOSED: [j][b]
__device__ unsigned g_cflag[128];                         // per-CTA step flags

__device__ __forceinline__ float softplus_b(float x){
    return (x > 20.f) ? x : log2f(1.f + exp2f(x));
}
__device__ __forceinline__ float sigmf(float x){ return 1.f/(1.f+expf(-x)); }

__device__ __forceinline__ ull ffma2(ull a, ull b, ull c){
    ull d;
    asm("fma.rn.f32x2 %0, %1, %2, %3;" : "=l"(d) : "l"(a), "l"(b), "l"(c));
    return d;
}
__device__ __forceinline__ float2 unpk(ull v){
    float lo, hi;
    asm("mov.b64 {%0, %1}, %2;" : "=f"(lo), "=f"(hi) : "l"(v));
    return make_float2(lo, hi);
}
__device__ __forceinline__ ull pk2(float lo, float hi){
    ull v;
    asm("mov.b64 %0, {%1, %2};" : "=l"(v) : "f"(lo), "f"(hi));
    return v;
}

// ---------------- cp.async / ldmatrix helpers ----------------
__device__ __forceinline__ uint32_t smem_u32(const void* p){
    uint32_t a;
    asm("{ .reg .u64 t; cvta.to.shared.u64 t, %1; cvt.u32.u64 %0, t; }" : "=r"(a) : "l"(p));
    return a;
}
__device__ __forceinline__ void cp16(uint32_t dst, const void* src){
    asm volatile("cp.async.cg.shared.global [%0], [%1], 16;" :: "r"(dst), "l"(src) : "memory");
}
#define CP_COMMIT() asm volatile("cp.async.commit_group;" ::: "memory")
template<int N> __device__ __forceinline__ void cp_wait(){
    asm volatile("cp.async.wait_group %0;" :: "n"(N) : "memory");
}
#define SWZ128(o) ((o) ^ (((o) >> 3) & 0x70))

__device__ __forceinline__ void ldsm4(uint32_t* r, uint32_t addr){
    asm volatile("ldmatrix.sync.aligned.m8n8.x4.shared.b16 {%0,%1,%2,%3}, [%4];"
        : "=r"(r[0]),"=r"(r[1]),"=r"(r[2]),"=r"(r[3]) : "r"(addr));
}

// ================= prep z =================
__global__ void k_prep_z(const int* __restrict__ x, const int* __restrict__ x_sl,
                         const float* __restrict__ eps, const float* __restrict__ emb)
{
    int row = blockIdx.x;
    int k   = threadIdx.x;
    int lin = row*256 + k;
    if (lin < Hn*Bn) g_hbuf[0][lin] = 0.f;
    if (lin < 128) g_cflag[lin] = 0u;
    int b = row / Tn, t = row % Tn;
    int xv = x[row];
    float mask = (t < x_sl[b]) ? 1.f : 0.f;
    float mu = emb[xv*TWOK + k];
    float sq = softplus_b(emb[xv*TWOK + Kn + k]);
    float e  = eps[row*Kn + k];
    float zv = (mu + sq*e) * mask;
    g_zb[row*Kn + k]         = __float2bfloat16(zv);
    g_ZZb[row*TWOK + k]      = __float2bfloat16(zv);
    g_ZZb[row*TWOK + Kn + k] = __float2bfloat16(zv*zv);
    float q = -HALF_LOG_2PI - logf(sq) - 0.5f*e*e;
    __shared__ float r1[256], r2[256];
    r1[k] = q; r2[k] = zv*zv;
    __syncthreads();
    for (int s = 128; s > 0; s >>= 1){
        if (k < s){ r1[k] += r1[k+s]; r2[k] += r2[k+s]; }
        __syncthreads();
    }
    if (k == 0){ g_qzlp[row] = r1[0]; g_sumz2[row] = r2[0]; }
}

// ================= prep v =================
__global__ void k_prep_v(const float* __restrict__ emb, const float* __restrict__ w_ih,
                         const float* __restrict__ w_prior, const float* __restrict__ w_gen)
{
    int v = blockIdx.x;
    int k = threadIdx.x;
    __shared__ float red[256];
    float mu = emb[v*TWOK + k];
    float sp = softplus_b(emb[v*TWOK + Kn + k]);
    float inv2 = 0.5f/(sp*sp);
    g_W2b[v*TWOK + k]      = __float2bfloat16(2.f*inv2*mu);
    g_W2b[v*TWOK + Kn + k] = __float2bfloat16(-inv2);
    g_wpb[v*Hn + k]       = __float2bfloat16(w_prior[(size_t)v*Hn + k]);
    g_wpb[v*Hn + 256 + k] = __float2bfloat16(w_prior[(size_t)v*Hn + 256 + k]);
    g_wgb[v*Kn + k]       = __float2bfloat16(w_gen[(size_t)v*Kn + k]);
    {
        int idx = v*256 + k;
        if (idx < G4n*Kn) g_wihb[idx] = __float2bfloat16(w_ih[idx]);
    }
    float c = -HALF_LOG_2PI - logf(sp) - mu*mu*inv2;
    red[k] = c;
    __syncthreads();
    for (int s = 128; s > 0; s >>= 1){
        if (k < s) red[k] += red[k+s];
        __syncthreads();
    }
    if (k == 0) g_cst[v] = red[0];
}

// ================= legacy bf16 mma (m16n8k16) =================
__device__ __forceinline__ void mma16(float* d, const uint32_t* a, const uint32_t* b){
    asm volatile("mma.sync.aligned.m16n8k16.row.col.f32.bf16.bf16.f32 "
        "{%0,%1,%2,%3}, {%4,%5,%6,%7}, {%8,%9}, {%0,%1,%2,%3};"
        : "+f"(d[0]),"+f"(d[1]),"+f"(d[2]),"+f"(d[3])
        : "r"(a[0]),"r"(a[1]),"r"(a[2]),"r"(a[3]), "r"(b[0]),"r"(b[1]));
}

// ---------------- x_proj GEMM ----------------
struct __align__(16) SmemTC {
    __nv_bfloat16 As[2][128][40];
    __nv_bfloat16 Bs[2][64][40];
};
__device__ __forceinline__ void ldA16s(const __nv_bfloat16* __restrict__ zb,
                                       int row0, int kt, int tid, uint4 (&rA)[2]){
    #pragma unroll
    for (int i=0;i<2;i++){
        int idx = tid + i*256;
        int row = idx>>2, q = idx&3;
        int grow = row0 + row;
        rA[i] = make_uint4(0u,0u,0u,0u);
        if ((grow & (Tn-1)) != 0)
            rA[i] = *(const uint4*)(zb + (size_t)(grow-1)*Kn + kt*32 + q*8);
    }
}
__device__ __forceinline__ void ldB16(const __nv_bfloat16* __restrict__ Bg, int ldb,
                                      int v0, int nmax, int kt, int tid, uint4& rB){
    int row = tid>>2, q = tid&3;
    int v = v0 + row; if (v >= nmax) v = nmax-1;
    rB = *(const uint4*)(Bg + (size_t)v*ldb + kt*32 + q*8);
}
__device__ __forceinline__ void stAB16(SmemTC* sm, int buf, int tid,
                                       const uint4 (&rA)[2], const uint4& rB){
    #pragma unroll
    for (int i=0;i<2;i++){
        int idx = tid + i*256; int row = idx>>2, q = idx&3;
        *(uint4*)&sm->As[buf][row][q*8] = rA[i];
    }
    { int row = tid>>2, q = tid&3;
      *(uint4*)&sm->Bs[buf][row][q*8] = rB; }
}
__device__ __forceinline__ void comp16L(uint32_t As_b, uint32_t Bs_b,
    uint32_t aoffP, uint32_t acolb, uint32_t boffP, uint32_t bcolb,
    float (&acc)[8][4])
{
    #pragma unroll
    for (int kk=0; kk<2; kk++){
        uint32_t af0[4], af1[4], b0[4], b1[4];
        uint32_t ac = kk*32 + acolb;
        uint32_t bc = kk*32 + bcolb;
        ldsm4(af0, As_b + aoffP + ac);
        ldsm4(af1, As_b + aoffP + 16*80 + ac);
        ldsm4(b0,  Bs_b + boffP + bc);
        ldsm4(b1,  Bs_b + boffP + 16*80 + bc);
        mma16(acc[0], af0, b0);
        mma16(acc[1], af0, b0+2);
        mma16(acc[2], af0, b1);
        mma16(acc[3], af0, b1+2);
        mma16(acc[4], af1, b0);
        mma16(acc[5], af1, b0+2);
        mma16(acc[6], af1, b1);
        mma16(acc[7], af1, b1+2);
    }
}

__global__ __launch_bounds__(256) void k_xproj16(const float* __restrict__ b_ih,
                                                 const float* __restrict__ b_hh)
{
    __shared__ SmemTC sm;
    int bcol = blockIdx.x * 64;
    int row0 = blockIdx.y * 128;
    int tid = threadIdx.x;
    int lane = tid&31, wid = tid>>5;
    int moff = (wid>>1)*32, noff = (wid&1)*32;
    int gr = lane>>2, tg = lane&3;
    int row_l = lane&7, sub = lane>>3;
    uint32_t aoffP = (uint32_t)(moff + (sub&1)*8 + row_l)*80u;
    uint32_t acolb = (uint32_t)((sub>>1)*16);
    uint32_t boffP = (uint32_t)(noff + (sub>>1)*8 + row_l)*80u;
    uint32_t bcolb = (uint32_t)((sub&1)*16);
    uint32_t As0 = smem_u32(&sm.As[0][0][0]);
    uint32_t Bs0 = smem_u32(&sm.Bs[0][0][0]);

    float acc[8][4] = {};
    {
        uint4 rA[2]; uint4 rB;
        ldA16s(g_zb,row0,0,tid,rA); ldB16(g_wihb,Kn,bcol,G4n,0,tid,rB);
        stAB16(&sm,0,tid,rA,rB);
        __syncthreads();
        const int nchunks = Kn/32;
        for (int kt=0; kt<nchunks; kt++){
            int cur = kt&1;
            bool more = (kt+1 < nchunks);
            if (more){ ldA16s(g_zb,row0,kt+1,tid,rA); ldB16(g_wihb,Kn,bcol,G4n,kt+1,tid,rB); }
            comp16L(As0 + cur*(128*80), Bs0 + cur*(64*80),
                    aoffP, acolb, boffP, bcolb, acc);
            if (more) stAB16(&sm,cur^1,tid,rA,rB);
            __syncthreads();
        }
    }
    // epilogue: store in LSTM-friendly layout [(js*128+t)*32+b][16r]
    #pragma unroll
    for (int nt=0; nt<4; nt++){
        #pragma unroll
        for (int c=0;c<2;c++){
            int col = bcol + noff + nt*8 + tg*2 + c;
            float bias = b_ih[col] + b_hh[col];
            int gate = col >> 9;
            int jc   = col & 511;
            int js   = jc >> 2, jj = jc & 3;
            int r    = gate*4 + jj;
            #pragma unroll
            for (int mt=0;mt<2;mt++)
                #pragma unroll
                for (int hf=0; hf<2; hf++){
                    int row = row0 + moff + mt*16 + gr + hf*8;
                    int b = row >> 7, tt = row & 127;
                    size_t addr = ((size_t)(js*Tn + tt)*32 + b)*16 + r;
                    g_xproj[addr] = acc[mt*4+nt][hf*2+c] + bias;
                }
        }
    }
}

// ================= persistent LSTM v5: per-CTA flags, 1 sync/step =================
// CTA js: 16 gate-rows for all 32 batches. 16 warps, warp = K-32nd (group kq = w).
// Producer: act warps -> named bar(128) -> tid0 threadfence + st.relaxed flag[js]=t+1.
// Consumer warp kq: lanes 0-7 poll flag[kq*8+lane] >= t, ld.acquire, syncwarp.
#define LSTM_WS   (16*512)
#define LSTM_PBS  (16*16*33)
#define LSTM_SMEM ((LSTM_WS + 2*LSTM_PBS)*(int)sizeof(float))

__global__ __launch_bounds__(512) void k_lstm_all(const float* __restrict__ w_hh)
{
    extern __shared__ float sm[];
    float* w_s  = sm;                       // [16 rows][512 k]
    float* pbuf = sm + LSTM_WS;             // [2][16 rows][16 kq][33]
    int tid = threadIdx.x, lane = tid & 31, w = tid >> 5;
    int js = blockIdx.x;

    for (int i = tid; i < 16*128; i += 512){
        int r = i >> 7, q = i & 127;
        int grow = (r>>2)*Hn + js*4 + (r&3);
        *(float4*)&w_s[r*512 + q*4] = *(const float4*)&w_hh[(size_t)grow*Hn + q*4];
    }

    int kq = w;                              // consume group kq: h rows [kq*32, kq*32+32)
    const float* wbase = w_s + kq*32;
    float c_reg = 0.f;                       // thread (b=lane, jj=w) for tid<128
    __syncthreads();                         // w_s ready

    for (int t = 0; t < Tn; t++){
        int par = t & 1;
        if (t > 0){
            if (lane < 8){
                const unsigned* fl = g_cflag + kq*8 + lane;
                unsigned v;
                do {
                    asm volatile("ld.relaxed.gpu.global.u32 %0, [%1];"
                                 : "=r"(v) : "l"(fl));
                } while (v < (unsigned)t);
                asm volatile("ld.acquire.gpu.global.u32 %0, [%1];"
                             : "=r"(v) : "l"(fl));
            }
            __syncwarp();
        }

        // activation warps preload xp(t) (hidden under dot)
        float xpv[4];
        if (w < 4){
            const float* xp = g_xproj + (size_t)(js*Tn + t)*512 + lane*16;
            xpv[0] = __ldcg(xp + w);
            xpv[1] = __ldcg(xp + 4 + w);
            xpv[2] = __ldcg(xp + 8 + w);
            xpv[3] = __ldcg(xp + 12 + w);
        }

        // dot: warp kq covers 32 k, all 16 rows
        {
            const float* hg = &g_hbuf[par][0] + (size_t)kq*32*32 + lane;
            ull acc[16];
            #pragma unroll
            for (int r=0;r<16;r++) acc[r] = 0ull;
            #pragma unroll
            for (int q = 0; q < 8; q++){
                float h0 = __ldcg(hg + (q*4+0)*32);
                float h1 = __ldcg(hg + (q*4+1)*32);
                float h2 = __ldcg(hg + (q*4+2)*32);
                float h3 = __ldcg(hg + (q*4+3)*32);
                ull hv01 = pk2(h0, h1);
                ull hv23 = pk2(h2, h3);
                #pragma unroll
                for (int r = 0; r < 16; r++){
                    ulonglong2 wv = *(const ulonglong2*)(wbase + r*512 + q*4);
                    acc[r] = ffma2(wv.x, hv01, acc[r]);
                    acc[r] = ffma2(wv.y, hv23, acc[r]);
                }
            }
            float* pb = pbuf + par*LSTM_PBS;
            #pragma unroll
            for (int r = 0; r < 16; r++){
                float2 u = unpk(acc[r]);
                pb[(r*16 + kq)*33 + lane] = u.x + u.y;
            }
        }
        __syncthreads();                      // pbuf[par] complete; protects reuse

        // activation (warps 0-3): thread (b=lane, jj=w)
        if (tid < 128){
            int b = lane, jj = w;
            int j = js*4 + jj;
            const float* pb = pbuf + par*LSTM_PBS;
            float g4[4];
            #pragma unroll
            for (int gate = 0; gate < 4; gate++){
                int r = gate*4 + jj;
                float s = xpv[gate];
                #pragma unroll
                for (int e = 0; e < 16; e++) s += pb[(r*16 + e)*33 + b];
                g4[gate] = s;
            }
            float c = c_reg;
            c = sigmf(g4[1])*c + sigmf(g4[0])*tanhf(g4[2]);
            float hv = sigmf(g4[3])*tanhf(c);
            c_reg = c;
            g_hbuf[par^1][j*32 + b] = hv;                        // transposed
            g_hb[(size_t)(b*Tn + t)*Hn + j] = __float2bfloat16(hv);
            asm volatile("bar.sync 1, 128;" ::: "memory");       // act warps done
            if (tid == 0){
                __threadfence();
                asm volatile("st.relaxed.gpu.global.u32 [%0], %1;"
                             :: "l"(g_cflag + js), "r"((unsigned)(t+1)) : "memory");
            }
        }
    }
}

// ================= k_big: cp.async + ldmatrix triple GEMM, 2 CTAs/SM =================
#define A_BYTES 16384
#define B_BYTES 8192
#define BUFSZ   (A_BYTES + B_BYTES)
#define DYN_BIG (2*BUFSZ)

__device__ __forceinline__ void issue_chunk(uint32_t abase, int buf, int tid,
    const __nv_bfloat16* __restrict__ Ag, const __nv_bfloat16* __restrict__ Bg,
    int lda, int local, int row0, int v0)
{
    uint32_t As = abase + buf*BUFSZ;
    uint32_t Bs = As + A_BYTES;
    #pragma unroll
    for (int i=0;i<4;i++){
        int idx = tid + i*256; int r = idx>>3, u = idx&7;
        cp16(As + SWZ128(r*128 + u*16), Ag + (size_t)(row0+r)*lda + local*64 + u*8);
    }
    #pragma unroll
    for (int i=0;i<2;i++){
        int idx = tid + i*256; int r = idx>>3, u = idx&7;
        int v = v0 + r; if (v >= Vn) v = Vn-1;
        cp16(Bs + SWZ128(r*128 + u*16), Bg + (size_t)v*lda + local*64 + u*8);
    }
    CP_COMMIT();
}

__device__ __forceinline__ void comp64L(uint32_t As_b, uint32_t Bs_b,
    uint32_t aoff, uint32_t acolb, uint32_t boff, uint32_t bcolb, uint32_t f,
    float (&acc)[8][4])
{
    #pragma unroll
    for (int kk=0; kk<4; kk++){
        uint32_t af0[4], af1[4], b0[4], b1[4];
        uint32_t ac = ((uint32_t)(kk*32) + acolb) ^ f;
        uint32_t bc = ((uint32_t)(kk*32) + bcolb) ^ f;
        ldsm4(af0, As_b + aoff + ac);
        ldsm4(af1, As_b + aoff + 2048u + ac);
        ldsm4(b0,  Bs_b + boff + bc);
        ldsm4(b1,  Bs_b + boff + 2048u + bc);
        mma16(acc[0], af0, b0);
        mma16(acc[1], af0, b0+2);
        mma16(acc[2], af0, b1);
        mma16(acc[3], af0, b1+2);
        mma16(acc[4], af1, b0);
        mma16(acc[5], af1, b0+2);
        mma16(acc[6], af1, b1);
        mma16(acc[7], af1, b1+2);
    }
}

__device__ __forceinline__ void chunk_src(int c, const __nv_bfloat16*& A,
                                          const __nv_bfloat16*& B, int& ld, int& loc)
{
    if (c < 8)      { A=g_hb;  B=g_wpb; ld=Hn;   loc=c;    }
    else if (c < 16){ A=g_ZZb; B=g_W2b; ld=TWOK; loc=c-8;  }
    else            { A=g_zb;  B=g_wgb; ld=Kn;   loc=c-16; }
}

__global__ __launch_bounds__(256,2) void k_big(
    const float* __restrict__ b_prior, const float* __restrict__ b_gen,
    const int* __restrict__ x)
{
    extern __shared__ __align__(128) char dynb[];
    __shared__ float sh_sum[128][3];
    __shared__ float sh_shift[128];
    __shared__ int   sh_xv[128];

    int vt = blockIdx.x, rt = blockIdx.y;
    int row0 = rt*128, v0 = vt*64;
    int tid = threadIdx.x;
    uint32_t abase = smem_u32(dynb);

    if (tid < 128){
        sh_shift[tid] = g_cst[0] - 0.5f*g_sumz2[row0+tid];
        sh_xv[tid]    = x[row0+tid];
        sh_sum[tid][0]=0.f; sh_sum[tid][1]=0.f; sh_sum[tid][2]=0.f;
    }

    int lane = tid&31, wid = tid>>5;
    int moff = (wid>>1)*32, noff = (wid&1)*32;
    int row_l = lane&7, sub = lane>>3;
    uint32_t f     = (uint32_t)(row_l*16);
    uint32_t aoff  = (uint32_t)(moff + (sub&1)*8 + row_l)*128u;
    uint32_t acolb = (uint32_t)((sub>>1)*16);
    uint32_t boff  = (uint32_t)(noff + (sub>>1)*8 + row_l)*128u;
    uint32_t bcolb = (uint32_t)((sub&1)*16);

    float accA[8][4] = {};
    float accB[8][4] = {};
    float rs1[4] = {}, rs2[4] = {}, rs3[4] = {};

    {
        const __nv_bfloat16 *Ag, *Bg; int lda, loc;
        chunk_src(0, Ag, Bg, lda, loc);
        issue_chunk(abase, 0, tid, Ag, Bg, lda, loc, row0, v0);
    }

    #pragma unroll 1
    for (int c = 0; c < 16; c++){
        cp_wait<0>();
        __syncthreads();
        {
            const __nv_bfloat16 *Ag, *Bg; int lda, loc;
            chunk_src(c+1, Ag, Bg, lda, loc);
            issue_chunk(abase, (c+1)&1, tid, Ag, Bg, lda, loc, row0, v0);
        }
        uint32_t As_b = abase + (c&1)*BUFSZ;
        uint32_t Bs_b = As_b + A_BYTES;
        if (c < 8) comp64L(As_b, Bs_b, aoff, acolb, boff, bcolb, f, accA);
        else       comp64L(As_b, Bs_b, aoff, acolb, boff, bcolb, f, accB);
    }

    // epilogue PM
    #pragma unroll
    for (int nt=0; nt<4; nt++){
        #pragma unroll
        for (int cc=0;cc<2;cc++){
            int n = noff + nt*8 + (lane&3)*2 + cc;
            int v = v0 + n;
            bool ok = v < Vn;
            int vc = ok ? v : (Vn-1);
            float bp = __ldg(&b_prior[vc]);
            float cv = g_cst[vc];
            #pragma unroll
            for (int mt=0;mt<2;mt++){
                #pragma unroll
                for (int hf=0; hf<2; hf++){
                    int rloc = moff + mt*16 + (lane>>2) + hf*8;
                    int ai = hf*2 + cc;
                    float s1 = accA[mt*4+nt][ai] + bp;
                    float s2 = s1 + cv + accB[mt*4+nt][ai] - sh_shift[rloc];
                    if (ok){
                        rs1[mt*2+hf] += __expf(s1);
                        rs2[mt*2+hf] += __expf(s2);
                    }
                }
            }
        }
    }
    #pragma unroll
    for (int i=0;i<8;i++)
        #pragma unroll
        for (int j=0;j<4;j++) accA[i][j] = 0.f;

    // phase G
    #pragma unroll 1
    for (int c = 16; c < 20; c++){
        cp_wait<0>();
        __syncthreads();
        if (c+1 < 20){
            const __nv_bfloat16 *Ag, *Bg; int lda, loc;
            chunk_src(c+1, Ag, Bg, lda, loc);
            issue_chunk(abase, (c+1)&1, tid, Ag, Bg, lda, loc, row0, v0);
        }
        uint32_t As_b = abase + (c&1)*BUFSZ;
        uint32_t Bs_b = As_b + A_BYTES;
        comp64L(As_b, Bs_b, aoff, acolb, boff, bcolb, f, accA);
    }

    // epilogue G
    #pragma unroll
    for (int nt=0; nt<4; nt++){
        #pragma unroll
        for (int cc=0;cc<2;cc++){
            int n = noff + nt*8 + (lane&3)*2 + cc;
            int v = v0 + n;
            bool ok = v < Vn;
            int vc = ok ? v : (Vn-1);
            float bg = __ldg(&b_gen[vc]);
            #pragma unroll
            for (int mt=0;mt<2;mt++){
                #pragma unroll
                for (int hf=0; hf<2; hf++){
                    int rloc = moff + mt*16 + (lane>>2) + hf*8;
                    int ai = hf*2 + cc;
                    float s3 = accA[mt*4+nt][ai] + bg;
                    if (ok){
                        rs3[mt*2+hf] += __expf(s3);
                        if (v == sh_xv[rloc]) g_tgt[row0 + rloc] = s3;
                    }
                }
            }
        }
    }

    #pragma unroll
    for (int lr=0; lr<4; lr++){
        float v0s = rs1[lr], v1s = rs2[lr], v2s = rs3[lr];
        v0s += __shfl_xor_sync(0xffffffffu, v0s, 1);
        v0s += __shfl_xor_sync(0xffffffffu, v0s, 2);
        v1s += __shfl_xor_sync(0xffffffffu, v1s, 1);
        v1s += __shfl_xor_sync(0xffffffffu, v1s, 2);
        v2s += __shfl_xor_sync(0xffffffffu, v2s, 1);
        v2s += __shfl_xor_sync(0xffffffffu, v2s, 2);
        if ((lane&3)==0){
            int mt = lr>>1, hf = lr&1;
            int rloc = moff + mt*16 + (lane>>2) + hf*8;
            atomicAdd(&sh_sum[rloc][0], v0s);
            atomicAdd(&sh_sum[rloc][1], v1s);
            atomicAdd(&sh_sum[rloc][2], v2s);
        }
    }
    __syncthreads();
    if (tid < 128){
        g_part[(0*NVT + vt)*BT + row0 + tid] = sh_sum[tid][0];
        g_part[(1*NVT + vt)*BT + row0 + tid] = sh_sum[tid][1];
        g_part[(2*NVT + vt)*BT + row0 + tid] = sh_sum[tid][2];
    }
}

// ---------------- per-row LSE finish ----------------
__global__ void k_lse(const int* __restrict__ x_sl)
{
    int row = blockIdx.x*256 + threadIdx.x;
    if (row >= BT) return;
    float S1=0.f, S2=0.f, S3=0.f;
    for (int vt = 0; vt < NVT; vt++){
        S1 += g_part[(0*NVT+vt)*BT + row];
        S2 += g_part[(1*NVT+vt)*BT + row];
        S3 += g_part[(2*NVT+vt)*BT + row];
    }
    int b = row / Tn, t = row % Tn;
    float shift = g_cst[0] - 0.5f*g_sumz2[row];
    float lse_p = logf(S1);
    float lse_m = shift + logf(S2);
    float lse_g = logf(S3);
    float mask = (t < x_sl[b]) ? 1.f : 0.f;
    g_contrib[row] = mask * (g_tgt[row] - lse_g - g_qzlp[row] + (lse_m - lse_p));
}

// ---------------- final scalar ----------------
__global__ void k_final(const int* __restrict__ x_sl, float* __restrict__ out)
{
    __shared__ float red[256];
    int tid = threadIdx.x;
    float s = 0.f;
    for (int i = tid; i < BT; i += 256) s += g_contrib[i];
    red[tid] = s; __syncthreads();
    for (int st = 128; st > 0; st >>= 1){
        if (tid < st) red[tid] += red[tid+st];
        __syncthreads();
    }
    if (tid == 0){
        int tot = 0;
        for (int b = 0; b < Bn; b++) tot += x_sl[b];
        out[0] = -red[0] / (float)tot;
    }
}

// ---------------- launch ----------------
extern "C" void kernel_launch(void* const* d_in, const int* in_sizes, int n_in,
                              void* d_out, int out_size)
{
    const int*   x       = (const int*)  d_in[0];
    const int*   x_sl    = (const int*)  d_in[1];
    const float* eps     = (const float*)d_in[2];
    const float* emb     = (const float*)d_in[3];
    const float* w_ih    = (const float*)d_in[4];
    const float* w_hh    = (const float*)d_in[5];
    const float* b_ih    = (const float*)d_in[6];
    const float* b_hh    = (const float*)d_in[7];
    const float* w_prior = (const float*)d_in[8];
    const float* b_prior = (const float*)d_in[9];
    const float* w_gen   = (const float*)d_in[10];
    const float* b_gen   = (const float*)d_in[11];
    float* out = (float*)d_out;

    cudaFuncSetAttribute(k_lstm_all, cudaFuncAttributeMaxDynamicSharedMemorySize, LSTM_SMEM);
    cudaFuncSetAttribute(k_big,      cudaFuncAttributeMaxDynamicSharedMemorySize, DYN_BIG);

    k_prep_z<<<BT, 256>>>(x, x_sl, eps, emb);                      // 1
    k_prep_v<<<Vn, 256>>>(emb, w_ih, w_prior, w_gen);              // 2
    k_xproj16<<<dim3(G4n/64, BT/128), 256>>>(b_ih, b_hh);          // 3
    k_lstm_all<<<128, 512, LSTM_SMEM>>>(w_hh);                     // 4  <- ncu target
    k_big<<<dim3(NVT, BT/128), 256, DYN_BIG>>>(b_prior, b_gen, x); // 5
    k_lse<<<BT/256, 256>>>(x_sl);                                  // 6
    k_final<<<1, 256>>>(x_sl, out);                                // 7
}

// round 17
// speedup vs baseline: 1.7313x; 1.7313x over previous
#include <cuda_runtime.h>
#include <cuda_bf16.h>
#include <cstdint>

#define Bn 32
#define Tn 128
#define Kn 256
#define Hn 512
#define Vn 10000
#define BT (Bn*Tn)
#define G4n (4*Hn)
#define TWOK (2*Kn)
#define NVT 157              // ceil(Vn/64)

#define HALF_LOG_2PI 0.918938533204672741780329736406f

typedef unsigned long long ull;

// ---------------- static scratch ----------------
__device__ __align__(16) __nv_bfloat16 g_zb[BT*Kn];      // 2 MB
__device__ __align__(16) __nv_bfloat16 g_ZZb[BT*TWOK];   // 4 MB [z | z^2]
__device__ __align__(16) __nv_bfloat16 g_hb[BT*Hn];      // 4 MB
__device__ __align__(16) __nv_bfloat16 g_W2b[Vn*TWOK];   // 10 MB
__device__ __align__(16) __nv_bfloat16 g_wpb[Vn*Hn];     // 10 MB
__device__ __align__(16) __nv_bfloat16 g_wgb[Vn*Kn];     // 5 MB
__device__ __align__(16) __nv_bfloat16 g_wihb[G4n*Kn];   // 1 MB
__device__ __align__(16) float g_xproj[BT*G4n];          // 32 MB, layout [(js*128+t)*32+b][16r]
__device__ float g_cst[Vn];
__device__ float g_qzlp[BT];
__device__ float g_sumz2[BT];
__device__ float g_tgt[BT];
__device__ float g_part[3*NVT*BT];
__device__ float g_contrib[BT];
__device__ __align__(16) float g_hbuf[2][Hn*Bn];         // TRANSPOSED: [j][b]
__device__ unsigned g_ctr16[16];                          // per-group (8 CTAs) step counters

__device__ __forceinline__ float softplus_b(float x){
    return (x > 20.f) ? x : log2f(1.f + exp2f(x));
}
__device__ __forceinline__ float sigmf(float x){ return 1.f/(1.f+expf(-x)); }

__device__ __forceinline__ ull ffma2(ull a, ull b, ull c){
    ull d;
    asm("fma.rn.f32x2 %0, %1, %2, %3;" : "=l"(d) : "l"(a), "l"(b), "l"(c));
    return d;
}
__device__ __forceinline__ float2 unpk(ull v){
    float lo, hi;
    asm("mov.b64 {%0, %1}, %2;" : "=f"(lo), "=f"(hi) : "l"(v));
    return make_float2(lo, hi);
}
__device__ __forceinline__ ull pk2(float lo, float hi){
    ull v;
    asm("mov.b64 %0, {%1, %2};" : "=l"(v) : "f"(lo), "f"(hi));
    return v;
}

// ---------------- cp.async / ldmatrix helpers ----------------
__device__ __forceinline__ uint32_t smem_u32(const void* p){
    uint32_t a;
    asm("{ .reg .u64 t; cvta.to.shared.u64 t, %1; cvt.u32.u64 %0, t; }" : "=r"(a) : "l"(p));
    return a;
}
__device__ __forceinline__ void cp16(uint32_t dst, const void* src){
    asm volatile("cp.async.cg.shared.global [%0], [%1], 16;" :: "r"(dst), "l"(src) : "memory");
}
#define CP_COMMIT() asm volatile("cp.async.commit_group;" ::: "memory")
template<int N> __device__ __forceinline__ void cp_wait(){
    asm volatile("cp.async.wait_group %0;" :: "n"(N) : "memory");
}
#define SWZ128(o) ((o) ^ (((o) >> 3) & 0x70))

__device__ __forceinline__ void ldsm4(uint32_t* r, uint32_t addr){
    asm volatile("ldmatrix.sync.aligned.m8n8.x4.shared.b16 {%0,%1,%2,%3}, [%4];"
        : "=r"(r[0]),"=r"(r[1]),"=r"(r[2]),"=r"(r[3]) : "r"(addr));
}

// ================= prep z =================
__global__ void k_prep_z(const int* __restrict__ x, const int* __restrict__ x_sl,
                         const float* __restrict__ eps, const float* __restrict__ emb)
{
    int row = blockIdx.x;
    int k   = threadIdx.x;
    int lin = row*256 + k;
    if (lin < Hn*Bn) g_hbuf[0][lin] = 0.f;
    if (lin < 16) g_ctr16[lin] = 0u;
    int b = row / Tn, t = row % Tn;
    int xv = x[row];
    float mask = (t < x_sl[b]) ? 1.f : 0.f;
    float mu = emb[xv*TWOK + k];
    float sq = softplus_b(emb[xv*TWOK + Kn + k]);
    float e  = eps[row*Kn + k];
    float zv = (mu + sq*e) * mask;
    g_zb[row*Kn + k]         = __float2bfloat16(zv);
    g_ZZb[row*TWOK + k]      = __float2bfloat16(zv);
    g_ZZb[row*TWOK + Kn + k] = __float2bfloat16(zv*zv);
    float q = -HALF_LOG_2PI - logf(sq) - 0.5f*e*e;
    __shared__ float r1[256], r2[256];
    r1[k] = q; r2[k] = zv*zv;
    __syncthreads();
    for (int s = 128; s > 0; s >>= 1){
        if (k < s){ r1[k] += r1[k+s]; r2[k] += r2[k+s]; }
        __syncthreads();
    }
    if (k == 0){ g_qzlp[row] = r1[0]; g_sumz2[row] = r2[0]; }
}

// ================= prep v =================
__global__ void k_prep_v(const float* __restrict__ emb, const float* __restrict__ w_ih,
                         const float* __restrict__ w_prior, const float* __restrict__ w_gen)
{
    int v = blockIdx.x;
    int k = threadIdx.x;
    __shared__ float red[256];
    float mu = emb[v*TWOK + k];
    float sp = softplus_b(emb[v*TWOK + Kn + k]);
    float inv2 = 0.5f/(sp*sp);
    g_W2b[v*TWOK + k]      = __float2bfloat16(2.f*inv2*mu);
    g_W2b[v*TWOK + Kn + k] = __float2bfloat16(-inv2);
    g_wpb[v*Hn + k]       = __float2bfloat16(w_prior[(size_t)v*Hn + k]);
    g_wpb[v*Hn + 256 + k] = __float2bfloat16(w_prior[(size_t)v*Hn + 256 + k]);
    g_wgb[v*Kn + k]       = __float2bfloat16(w_gen[(size_t)v*Kn + k]);
    {
        int idx = v*256 + k;
        if (idx < G4n*Kn) g_wihb[idx] = __float2bfloat16(w_ih[idx]);
    }
    float c = -HALF_LOG_2PI - logf(sp) - mu*mu*inv2;
    red[k] = c;
    __syncthreads();
    for (int s = 128; s > 0; s >>= 1){
        if (k < s) red[k] += red[k+s];
        __syncthreads();
    }
    if (k == 0) g_cst[v] = red[0];
}

// ================= legacy bf16 mma (m16n8k16) =================
__device__ __forceinline__ void mma16(float* d, const uint32_t* a, const uint32_t* b){
    asm volatile("mma.sync.aligned.m16n8k16.row.col.f32.bf16.bf16.f32 "
        "{%0,%1,%2,%3}, {%4,%5,%6,%7}, {%8,%9}, {%0,%1,%2,%3};"
        : "+f"(d[0]),"+f"(d[1]),"+f"(d[2]),"+f"(d[3])
        : "r"(a[0]),"r"(a[1]),"r"(a[2]),"r"(a[3]), "r"(b[0]),"r"(b[1]));
}

// ---------------- x_proj GEMM ----------------
struct __align__(16) SmemTC {
    __nv_bfloat16 As[2][128][40];
    __nv_bfloat16 Bs[2][64][40];
};
__device__ __forceinline__ void ldA16s(const __nv_bfloat16* __restrict__ zb,
                                       int row0, int kt, int tid, uint4 (&rA)[2]){
    #pragma unroll
    for (int i=0;i<2;i++){
        int idx = tid + i*256;
        int row = idx>>2, q = idx&3;
        int grow = row0 + row;
        rA[i] = make_uint4(0u,0u,0u,0u);
        if ((grow & (Tn-1)) != 0)
            rA[i] = *(const uint4*)(zb + (size_t)(grow-1)*Kn + kt*32 + q*8);
    }
}
__device__ __forceinline__ void ldB16(const __nv_bfloat16* __restrict__ Bg, int ldb,
                                      int v0, int nmax, int kt, int tid, uint4& rB){
    int row = tid>>2, q = tid&3;
    int v = v0 + row; if (v >= nmax) v = nmax-1;
    rB = *(const uint4*)(Bg + (size_t)v*ldb + kt*32 + q*8);
}
__device__ __forceinline__ void stAB16(SmemTC* sm, int buf, int tid,
                                       const uint4 (&rA)[2], const uint4& rB){
    #pragma unroll
    for (int i=0;i<2;i++){
        int idx = tid + i*256; int row = idx>>2, q = idx&3;
        *(uint4*)&sm->As[buf][row][q*8] = rA[i];
    }
    { int row = tid>>2, q = tid&3;
      *(uint4*)&sm->Bs[buf][row][q*8] = rB; }
}
__device__ __forceinline__ void comp16L(uint32_t As_b, uint32_t Bs_b,
    uint32_t aoffP, uint32_t acolb, uint32_t boffP, uint32_t bcolb,
    float (&acc)[8][4])
{
    #pragma unroll
    for (int kk=0; kk<2; kk++){
        uint32_t af0[4], af1[4], b0[4], b1[4];
        uint32_t ac = kk*32 + acolb;
        uint32_t bc = kk*32 + bcolb;
        ldsm4(af0, As_b + aoffP + ac);
        ldsm4(af1, As_b + aoffP + 16*80 + ac);
        ldsm4(b0,  Bs_b + boffP + bc);
        ldsm4(b1,  Bs_b + boffP + 16*80 + bc);
        mma16(acc[0], af0, b0);
        mma16(acc[1], af0, b0+2);
        mma16(acc[2], af0, b1);
        mma16(acc[3], af0, b1+2);
        mma16(acc[4], af1, b0);
        mma16(acc[5], af1, b0+2);
        mma16(acc[6], af1, b1);
        mma16(acc[7], af1, b1+2);
    }
}

__global__ __launch_bounds__(256) void k_xproj16(const float* __restrict__ b_ih,
                                                 const float* __restrict__ b_hh)
{
    __shared__ SmemTC sm;
    int bcol = blockIdx.x * 64;
    int row0 = blockIdx.y * 128;
    int tid = threadIdx.x;
    int lane = tid&31, wid = tid>>5;
    int moff = (wid>>1)*32, noff = (wid&1)*32;
    int gr = lane>>2, tg = lane&3;
    int row_l = lane&7, sub = lane>>3;
    uint32_t aoffP = (uint32_t)(moff + (sub&1)*8 + row_l)*80u;
    uint32_t acolb = (uint32_t)((sub>>1)*16);
    uint32_t boffP = (uint32_t)(noff + (sub>>1)*8 + row_l)*80u;
    uint32_t bcolb = (uint32_t)((sub&1)*16);
    uint32_t As0 = smem_u32(&sm.As[0][0][0]);
    uint32_t Bs0 = smem_u32(&sm.Bs[0][0][0]);

    float acc[8][4] = {};
    {
        uint4 rA[2]; uint4 rB;
        ldA16s(g_zb,row0,0,tid,rA); ldB16(g_wihb,Kn,bcol,G4n,0,tid,rB);
        stAB16(&sm,0,tid,rA,rB);
        __syncthreads();
        const int nchunks = Kn/32;
        for (int kt=0; kt<nchunks; kt++){
            int cur = kt&1;
            bool more = (kt+1 < nchunks);
            if (more){ ldA16s(g_zb,row0,kt+1,tid,rA); ldB16(g_wihb,Kn,bcol,G4n,kt+1,tid,rB); }
            comp16L(As0 + cur*(128*80), Bs0 + cur*(64*80),
                    aoffP, acolb, boffP, bcolb, acc);
            if (more) stAB16(&sm,cur^1,tid,rA,rB);
            __syncthreads();
        }
    }
    // epilogue: store in LSTM-friendly layout [(js*128+t)*32+b][16r]
    #pragma unroll
    for (int nt=0; nt<4; nt++){
        #pragma unroll
        for (int c=0;c<2;c++){
            int col = bcol + noff + nt*8 + tg*2 + c;
            float bias = b_ih[col] + b_hh[col];
            int gate = col >> 9;
            int jc   = col & 511;
            int js   = jc >> 2, jj = jc & 3;
            int r    = gate*4 + jj;
            #pragma unroll
            for (int mt=0;mt<2;mt++)
                #pragma unroll
                for (int hf=0; hf<2; hf++){
                    int row = row0 + moff + mt*16 + gr + hf*8;
                    int b = row >> 7, tt = row & 127;
                    size_t addr = ((size_t)(js*Tn + tt)*32 + b)*16 + r;
                    g_xproj[addr] = acc[mt*4+nt][hf*2+c] + bias;
                }
        }
    }
}

// ================= persistent LSTM v6: R14 structure + 16 group counters =================
// CTA js: 16 gate-rows for all 32 batches. 16 warps, warp = K-32nd (consumes group kq=w).
// Producer (unchanged from R14): all-thread __threadfence, __syncthreads, tid0 ONE
// atomicAdd -> g_ctr16[js>>3]. Consumer: warp kq lane0 polls g_ctr16[kq] >= t*8,
// ld.acquire, __syncwarp. 2 syncthreads/step.
#define LSTM_WS   (16*512)
#define LSTM_PB   (16*16*33)
#define LSTM_XP   (2*512)
#define LSTM_SMEM ((LSTM_WS + LSTM_PB + LSTM_XP)*(int)sizeof(float))

__global__ __launch_bounds__(512) void k_lstm_all(const float* __restrict__ w_hh)
{
    extern __shared__ float sm[];
    float* w_s  = sm;                       // [16 rows][512 k]
    float* pbuf = sm + LSTM_WS;             // [16 rows][16 kq][33]
    float* xp_s = pbuf + LSTM_PB;           // [2][512]
    int tid = threadIdx.x, lane = tid & 31, w = tid >> 5;
    int js = blockIdx.x;

    for (int i = tid; i < 16*128; i += 512){
        int r = i >> 7, q = i & 127;
        int grow = (r>>2)*Hn + js*4 + (r&3);
        *(float4*)&w_s[r*512 + q*4] = *(const float4*)&w_hh[(size_t)grow*Hn + q*4];
    }

    uint32_t xp_base = smem_u32(xp_s);
    if (tid < 128)
        cp16(xp_base + tid*16, g_xproj + (size_t)(js*Tn + 0)*512 + tid*4);
    CP_COMMIT();

    int kq = w;                              // K-32nd: k in [kq*32, kq*32+32)
    const float* wbase = w_s + kq*32;
    unsigned* myctr = g_ctr16 + kq;          // group this warp consumes
    unsigned* relctr = g_ctr16 + (js >> 3);  // group this CTA produces
    float c_reg = 0.f;                       // thread (b=lane, jj=w), tid<128
    __syncthreads();                         // w_s ready

    for (int t = 0; t < Tn; t++){
        int par = t & 1;
        if (t > 0){
            unsigned target = (unsigned)t * 8u;
            if (lane == 0){
                unsigned v;
                do {
                    asm volatile("ld.relaxed.gpu.global.u32 %0, [%1];"
                                 : "=r"(v) : "l"(myctr));
                } while (v < target);
                asm volatile("ld.acquire.gpu.global.u32 %0, [%1];"
                             : "=r"(v) : "l"(myctr));
            }
            __syncwarp();
        }
        // prefetch xproj for t+1
        if (t+1 < Tn && tid < 128)
            cp16(xp_base + ((t+1)&1)*2048 + tid*16,
                 g_xproj + (size_t)(js*Tn + (t+1))*512 + tid*4);
        CP_COMMIT();

        // dot: warp kq covers 32 k, all 16 rows; h via coalesced L2 loads
        {
            const float* hg = &g_hbuf[par][0] + (size_t)kq*32*32 + lane;
            ull acc[16];
            #pragma unroll
            for (int r=0;r<16;r++) acc[r] = 0ull;
            #pragma unroll
            for (int q = 0; q < 8; q++){
                float h0 = __ldcg(hg + (q*4+0)*32);
                float h1 = __ldcg(hg + (q*4+1)*32);
                float h2 = __ldcg(hg + (q*4+2)*32);
                float h3 = __ldcg(hg + (q*4+3)*32);
                ull hv01 = pk2(h0, h1);
                ull hv23 = pk2(h2, h3);
                #pragma unroll
                for (int r = 0; r < 16; r++){
                    ulonglong2 wv = *(const ulonglong2*)(wbase + r*512 + q*4);
                    acc[r] = ffma2(wv.x, hv01, acc[r]);
                    acc[r] = ffma2(wv.y, hv23, acc[r]);
                }
            }
            #pragma unroll
            for (int r = 0; r < 16; r++){
                float2 u = unpk(acc[r]);
                pbuf[(r*16 + kq)*33 + lane] = u.x + u.y;
            }
        }
        cp_wait<1>();        // xp(t) resident
        __syncthreads();     // pbuf complete

        // activation (tid < 128): thread (b=lane, jj=w)
        if (tid < 128){
            int b = lane, jj = w;
            int j = js*4 + jj;
            const float* xp = xp_s + (t&1)*512 + b*16;
            float g4[4];
            #pragma unroll
            for (int gate = 0; gate < 4; gate++){
                int r = gate*4 + jj;
                float s = xp[r];
                #pragma unroll
                for (int e = 0; e < 16; e++) s += pbuf[(r*16 + e)*33 + b];
                g4[gate] = s;
            }
            float c = c_reg;
            c = sigmf(g4[1])*c + sigmf(g4[0])*tanhf(g4[2]);
            float hv = sigmf(g4[3])*tanhf(c);
            c_reg = c;
            g_hbuf[par^1][j*32 + b] = hv;                        // transposed
            g_hb[(size_t)(b*Tn + t)*Hn + j] = __float2bfloat16(hv);
        }
        __threadfence();
        __syncthreads();     // h writes done + pbuf reads done (protects reuse)
        if (tid == 0) atomicAdd(relctr, 1u);
    }
}

// ================= k_big: cp.async + ldmatrix triple GEMM, 2 CTAs/SM =================
#define A_BYTES 16384
#define B_BYTES 8192
#define BUFSZ   (A_BYTES + B_BYTES)
#define DYN_BIG (2*BUFSZ)

__device__ __forceinline__ void issue_chunk(uint32_t abase, int buf, int tid,
    const __nv_bfloat16* __restrict__ Ag, const __nv_bfloat16* __restrict__ Bg,
    int lda, int local, int row0, int v0)
{
    uint32_t As = abase + buf*BUFSZ;
    uint32_t Bs = As + A_BYTES;
    #pragma unroll
    for (int i=0;i<4;i++){
        int idx = tid + i*256; int r = idx>>3, u = idx&7;
        cp16(As + SWZ128(r*128 + u*16), Ag + (size_t)(row0+r)*lda + local*64 + u*8);
    }
    #pragma unroll
    for (int i=0;i<2;i++){
        int idx = tid + i*256; int r = idx>>3, u = idx&7;
        int v = v0 + r; if (v >= Vn) v = Vn-1;
        cp16(Bs + SWZ128(r*128 + u*16), Bg + (size_t)v*lda + local*64 + u*8);
    }
    CP_COMMIT();
}

__device__ __forceinline__ void comp64L(uint32_t As_b, uint32_t Bs_b,
    uint32_t aoff, uint32_t acolb, uint32_t boff, uint32_t bcolb, uint32_t f,
    float (&acc)[8][4])
{
    #pragma unroll
    for (int kk=0; kk<4; kk++){
        uint32_t af0[4], af1[4], b0[4], b1[4];
        uint32_t ac = ((uint32_t)(kk*32) + acolb) ^ f;
        uint32_t bc = ((uint32_t)(kk*32) + bcolb) ^ f;
        ldsm4(af0, As_b + aoff + ac);
        ldsm4(af1, As_b + aoff + 2048u + ac);
        ldsm4(b0,  Bs_b + boff + bc);
        ldsm4(b1,  Bs_b + boff + 2048u + bc);
        mma16(acc[0], af0, b0);
        mma16(acc[1], af0, b0+2);
        mma16(acc[2], af0, b1);
        mma16(acc[3], af0, b1+2);
        mma16(acc[4], af1, b0);
        mma16(acc[5], af1, b0+2);
        mma16(acc[6], af1, b1);
        mma16(acc[7], af1, b1+2);
    }
}

__device__ __forceinline__ void chunk_src(int c, const __nv_bfloat16*& A,
                                          const __nv_bfloat16*& B, int& ld, int& loc)
{
    if (c < 8)      { A=g_hb;  B=g_wpb; ld=Hn;   loc=c;    }
    else if (c < 16){ A=g_ZZb; B=g_W2b; ld=TWOK; loc=c-8;  }
    else            { A=g_zb;  B=g_wgb; ld=Kn;   loc=c-16; }
}

__global__ __launch_bounds__(256,2) void k_big(
    const float* __restrict__ b_prior, const float* __restrict__ b_gen,
    const int* __restrict__ x)
{
    extern __shared__ __align__(128) char dynb[];
    __shared__ float sh_sum[128][3];
    __shared__ float sh_shift[128];
    __shared__ int   sh_xv[128];

    int vt = blockIdx.x, rt = blockIdx.y;
    int row0 = rt*128, v0 = vt*64;
    int tid = threadIdx.x;
    uint32_t abase = smem_u32(dynb);

    if (tid < 128){
        sh_shift[tid] = g_cst[0] - 0.5f*g_sumz2[row0+tid];
        sh_xv[tid]    = x[row0+tid];
        sh_sum[tid][0]=0.f; sh_sum[tid][1]=0.f; sh_sum[tid][2]=0.f;
    }

    int lane = tid&31, wid = tid>>5;
    int moff = (wid>>1)*32, noff = (wid&1)*32;
    int row_l = lane&7, sub = lane>>3;
    uint32_t f     = (uint32_t)(row_l*16);
    uint32_t aoff  = (uint32_t)(moff + (sub&1)*8 + row_l)*128u;
    uint32_t acolb = (uint32_t)((sub>>1)*16);
    uint32_t boff  = (uint32_t)(noff + (sub>>1)*8 + row_l)*128u;
    uint32_t bcolb = (uint32_t)((sub&1)*16);

    float accA[8][4] = {};
    float accB[8][4] = {};
    float rs1[4] = {}, rs2[4] = {}, rs3[4] = {};

    {
        const __nv_bfloat16 *Ag, *Bg; int lda, loc;
        chunk_src(0, Ag, Bg, lda, loc);
        issue_chunk(abase, 0, tid, Ag, Bg, lda, loc, row0, v0);
    }

    #pragma unroll 1
    for (int c = 0; c < 16; c++){
        cp_wait<0>();
        __syncthreads();
        {
            const __nv_bfloat16 *Ag, *Bg; int lda, loc;
            chunk_src(c+1, Ag, Bg, lda, loc);
            issue_chunk(abase, (c+1)&1, tid, Ag, Bg, lda, loc, row0, v0);
        }
        uint32_t As_b = abase + (c&1)*BUFSZ;
        uint32_t Bs_b = As_b + A_BYTES;
        if (c < 8) comp64L(As_b, Bs_b, aoff, acolb, boff, bcolb, f, accA);
        else       comp64L(As_b, Bs_b, aoff, acolb, boff, bcolb, f, accB);
    }

    // epilogue PM
    #pragma unroll
    for (int nt=0; nt<4; nt++){
        #pragma unroll
        for (int cc=0;cc<2;cc++){
            int n = noff + nt*8 + (lane&3)*2 + cc;
            int v = v0 + n;
            bool ok = v < Vn;
            int vc = ok ? v : (Vn-1);
            float bp = __ldg(&b_prior[vc]);
            float cv = g_cst[vc];
            #pragma unroll
            for (int mt=0;mt<2;mt++){
                #pragma unroll
                for (int hf=0; hf<2; hf++){
                    int rloc = moff + mt*16 + (lane>>2) + hf*8;
                    int ai = hf*2 + cc;
                    float s1 = accA[mt*4+nt][ai] + bp;
                    float s2 = s1 + cv + accB[mt*4+nt][ai] - sh_shift[rloc];
                    if (ok){
                        rs1[mt*2+hf] += __expf(s1);
                        rs2[mt*2+hf] += __expf(s2);
                    }
                }
            }
        }
    }
    #pragma unroll
    for (int i=0;i<8;i++)
        #pragma unroll
        for (int j=0;j<4;j++) accA[i][j] = 0.f;

    // phase G
    #pragma unroll 1
    for (int c = 16; c < 20; c++){
        cp_wait<0>();
        __syncthreads();
        if (c+1 < 20){
            const __nv_bfloat16 *Ag, *Bg; int lda, loc;
            chunk_src(c+1, Ag, Bg, lda, loc);
            issue_chunk(abase, (c+1)&1, tid, Ag, Bg, lda, loc, row0, v0);
        }
        uint32_t As_b = abase + (c&1)*BUFSZ;
        uint32_t Bs_b = As_b + A_BYTES;
        comp64L(As_b, Bs_b, aoff, acolb, boff, bcolb, f, accA);
    }

    // epilogue G
    #pragma unroll
    for (int nt=0; nt<4; nt++){
        #pragma unroll
        for (int cc=0;cc<2;cc++){
            int n = noff + nt*8 + (lane&3)*2 + cc;
            int v = v0 + n;
            bool ok = v < Vn;
            int vc = ok ? v : (Vn-1);
            float bg = __ldg(&b_gen[vc]);
            #pragma unroll
            for (int mt=0;mt<2;mt++){
                #pragma unroll
                for (int hf=0; hf<2; hf++){
                    int rloc = moff + mt*16 + (lane>>2) + hf*8;
                    int ai = hf*2 + cc;
                    float s3 = accA[mt*4+nt][ai] + bg;
                    if (ok){
                        rs3[mt*2+hf] += __expf(s3);
                        if (v == sh_xv[rloc]) g_tgt[row0 + rloc] = s3;
                    }
                }
            }
        }
    }

    #pragma unroll
    for (int lr=0; lr<4; lr++){
        float v0s = rs1[lr], v1s = rs2[lr], v2s = rs3[lr];
        v0s += __shfl_xor_sync(0xffffffffu, v0s, 1);
        v0s += __shfl_xor_sync(0xffffffffu, v0s, 2);
        v1s += __shfl_xor_sync(0xffffffffu, v1s, 1);
        v1s += __shfl_xor_sync(0xffffffffu, v1s, 2);
        v2s += __shfl_xor_sync(0xffffffffu, v2s, 1);
        v2s += __shfl_xor_sync(0xffffffffu, v2s, 2);
        if ((lane&3)==0){
            int mt = lr>>1, hf = lr&1;
            int rloc = moff + mt*16 + (lane>>2) + hf*8;
            atomicAdd(&sh_sum[rloc][0], v0s);
            atomicAdd(&sh_sum[rloc][1], v1s);
            atomicAdd(&sh_sum[rloc][2], v2s);
        }
    }
    __syncthreads();
    if (tid < 128){
        g_part[(0*NVT + vt)*BT + row0 + tid] = sh_sum[tid][0];
        g_part[(1*NVT + vt)*BT + row0 + tid] = sh_sum[tid][1];
        g_part[(2*NVT + vt)*BT + row0 + tid] = sh_sum[tid][2];
    }
}

// ---------------- per-row LSE finish ----------------
__global__ void k_lse(const int* __restrict__ x_sl)
{
    int row = blockIdx.x*256 + threadIdx.x;
    if (row >= BT) return;
    float S1=0.f, S2=0.f, S3=0.f;
    for (int vt = 0; vt < NVT; vt++){
        S1 += g_part[(0*NVT+vt)*BT + row];
        S2 += g_part[(1*NVT+vt)*BT + row];
        S3 += g_part[(2*NVT+vt)*BT + row];
    }
    int b = row / Tn, t = row % Tn;
    float shift = g_cst[0] - 0.5f*g_sumz2[row];
    float lse_p = logf(S1);
    float lse_m = shift + logf(S2);
    float lse_g = logf(S3);
    float mask = (t < x_sl[b]) ? 1.f : 0.f;
    g_contrib[row] = mask * (g_tgt[row] - lse_g - g_qzlp[row] + (lse_m - lse_p));
}

// ---------------- final scalar ----------------
__global__ void k_final(const int* __restrict__ x_sl, float* __restrict__ out)
{
    __shared__ float red[256];
    int tid = threadIdx.x;
    float s = 0.f;
    for (int i = tid; i < BT; i += 256) s += g_contrib[i];
    red[tid] = s; __syncthreads();
    for (int st = 128; st > 0; st >>= 1){
        if (tid < st) red[tid] += red[tid+st];
        __syncthreads();
    }
    if (tid == 0){
        int tot = 0;
        for (int b = 0; b < Bn; b++) tot += x_sl[b];
        out[0] = -red[0] / (float)tot;
    }
}

// ---------------- launch ----------------
extern "C" void kernel_launch(void* const* d_in, const int* in_sizes, int n_in,
                              void* d_out, int out_size)
{
    const int*   x       = (const int*)  d_in[0];
    const int*   x_sl    = (const int*)  d_in[1];
    const float* eps     = (const float*)d_in[2];
    const float* emb     = (const float*)d_in[3];
    const float* w_ih    = (const float*)d_in[4];
    const float* w_hh    = (const float*)d_in[5];
    const float* b_ih    = (const float*)d_in[6];
    const float* b_hh    = (const float*)d_in[7];
    const float* w_prior = (const float*)d_in[8];
    const float* b_prior = (const float*)d_in[9];
    const float* w_gen   = (const float*)d_in[10];
    const float* b_gen   = (const float*)d_in[11];
    float* out = (float*)d_out;

    cudaFuncSetAttribute(k_lstm_all, cudaFuncAttributeMaxDynamicSharedMemorySize, LSTM_SMEM);
    cudaFuncSetAttribute(k_big,      cudaFuncAttributeMaxDynamicSharedMemorySize, DYN_BIG);

    k_prep_z<<<BT, 256>>>(x, x_sl, eps, emb);                      // 1
    k_prep_v<<<Vn, 256>>>(emb, w_ih, w_prior, w_gen);              // 2
    k_xproj16<<<dim3(G4n/64, BT/128), 256>>>(b_ih, b_hh);          // 3
    k_lstm_all<<<128, 512, LSTM_SMEM>>>(w_hh);                     // 4  <- ncu target
    k_big<<<dim3(NVT, BT/128), 256, DYN_BIG>>>(b_prior, b_gen, x); // 5
    k_lse<<<BT/256, 256>>>(x_sl);                                  // 6
    k_final<<<1, 256>>>(x_sl, out);                                // 7
}